// round 14
// baseline (speedup 1.0000x reference)
#include <cuda_runtime.h>
#include <cuda_fp16.h>
#include <cstdint>

#define NB 2
#define NN 384
#define TFv 22
#define POSv 32
#define TPROJv 33
#define CSv 256
#define CZv 128
#define LN_EPS 1e-5f
#define PI_F 3.14159265358979323846f

__device__ float g_table[2048 * CZv];
__device__ float g_eL[NB * NN * CZv];
__device__ float g_eR[NB * NN * CZv];
__device__ __half g_W1f[CZv * CZv], g_W2f[CZv * CZv];

// ---------------------------------------------------------------------------
// helpers
// ---------------------------------------------------------------------------
__device__ __forceinline__ uint32_t smem_u32(const void* p) {
    uint32_t a;
    asm("{ .reg .u64 t; cvta.to.shared.u64 t, %1; cvt.u32.u64 %0, t; }"
        : "=r"(a) : "l"(p));
    return a;
}
__device__ __forceinline__ uint32_t packh2(float r0, float r1) {
    __half2 v = __floats2half2_rn(r0, r1);
    return *reinterpret_cast<uint32_t*>(&v);
}
__device__ __forceinline__ void mma16816(float* c, uint32_t a0, uint32_t a1,
                                         uint32_t a2, uint32_t a3,
                                         uint32_t b0, uint32_t b1) {
    asm volatile(
        "mma.sync.aligned.m16n8k16.row.col.f32.f16.f16.f32 "
        "{%0,%1,%2,%3}, {%4,%5,%6,%7}, {%8,%9}, {%0,%1,%2,%3};"
        : "+f"(c[0]), "+f"(c[1]), "+f"(c[2]), "+f"(c[3])
        : "r"(a0), "r"(a1), "r"(a2), "r"(a3), "r"(b0), "r"(b1));
}
__device__ __forceinline__ void ldsm_x4(uint32_t& r0, uint32_t& r1,
                                        uint32_t& r2, uint32_t& r3, uint32_t addr) {
    asm volatile("ldmatrix.sync.aligned.m8n8.x4.shared.b16 {%0,%1,%2,%3}, [%4];"
                 : "=r"(r0), "=r"(r1), "=r"(r2), "=r"(r3) : "r"(addr));
}

// ---------------------------------------------------------------------------
// Fused setup kernel (unchanged — correctness proven).
// ---------------------------------------------------------------------------
#define NR 8
#define TBLK 1024
#define NODEB (NB * NN / NR)   // 96

__global__ __launch_bounds__(256) void setup_kernel(
    const int* __restrict__ seq_idx, const float* __restrict__ seq_feat,
    const float* __restrict__ timestep, const float* __restrict__ frame_mask,
    const float* __restrict__ W_npos, const float* __restrict__ b_npos,
    const float* __restrict__ W_ntf, const float* __restrict__ b_ntf,
    const float* __restrict__ W_ntime, const float* __restrict__ b_ntime,
    const float* __restrict__ W_n1, const float* __restrict__ b_n1,
    const float* __restrict__ W_n2, const float* __restrict__ b_n2,
    const float* __restrict__ g_n, const float* __restrict__ be_n,
    const float* __restrict__ W_epos, const float* __restrict__ b_epos,
    const float* __restrict__ b_etf, const float* __restrict__ b_etime,
    const float* __restrict__ W_etf, const float* __restrict__ W_etime,
    const float* __restrict__ W_e1, const float* __restrict__ W_e2,
    float* __restrict__ out_seq) {
    __shared__ float su[4352];
    const int tid = threadIdx.x;
    const int bid = blockIdx.x;

    if (bid < TBLK) {
        float* sWe = su;
        float* emb = su + 4224;
        const int half = tid >> 7, c = tid & 127;
        for (int m = tid; m < CZv * POSv; m += 256)
            sWe[(m >> 5) * 33 + (m & 31)] = W_epos[m];
        const int relv = bid * 2 + half - 1000;
        if (c < 16) {
            float p = powf(2056.0f, (float)c * (1.0f / 16.0f));
            float ang = ((float)relv * PI_F) / p;
            emb[half * 32 + c] = sinf(ang);
            emb[half * 32 + c + 16] = cosf(ang);
        }
        __syncthreads();
        float acc = b_epos[c] + b_etf[c] + b_etime[c];
#pragma unroll
        for (int k = 0; k < POSv; k++) acc += emb[half * 32 + k] * sWe[c * 33 + k];
        g_table[(bid * 2 + half) * CZv + c] = acc;
        return;
    }
    if (bid >= TBLK + NODEB) {
        int t = (bid - TBLK - NODEB) * 256 + tid;
        g_W1f[t] = __float2half_rn(W_e1[t]);
        g_W2f[t] = __float2half_rn(W_e2[t]);
        return;
    }

    float (*spemb)[POSv] = (float(*)[POSv])su;
    float (*stemb)[36] = (float(*)[36])(su + 256);
    float (*sfeat)[24] = (float(*)[24])(su + 544);
    float (*sx)[CSv] = (float(*)[CSv])(su + 736);
    const int row0 = (bid - TBLK) * NR;

    {
        const int r = tid >> 5, j = tid & 31;
        const int row = row0 + r;
        const int b = row / NN;
        if (j < TFv) sfeat[r][j] = seq_feat[row * TFv + j];
        if (j < 16) {
            float p = powf(2056.0f, (float)j * (1.0f / 16.0f));
            float ang = ((float)seq_idx[row] * PI_F) / p;
            spemb[r][j] = sinf(ang);
            spemb[r][j + 16] = cosf(ang);
            float fm = frame_mask[row];
            float tt = timestep[b] * fm;
            float fr = expf(-0.6140226914650789f * (float)j);
            float a2 = tt * fr;
            stemb[r][j] = sinf(a2);
            stemb[r][j + 16] = cosf(a2);
            if (j == 0) stemb[r][32] = fm;
        }
    }
    __syncthreads();

    const int c = tid;
    float acc[NR];
    {
        float base = b_npos[c] + b_ntf[c] + b_ntime[c];
#pragma unroll
        for (int r = 0; r < NR; r++) acc[r] = base;
    }
#pragma unroll
    for (int k = 0; k < POSv; k++) {
        float wv = W_npos[c * POSv + k];
#pragma unroll
        for (int r = 0; r < NR; r++) acc[r] += spemb[r][k] * wv;
    }
#pragma unroll
    for (int k = 0; k < TFv; k++) {
        float wv = W_ntf[c * TFv + k];
#pragma unroll
        for (int r = 0; r < NR; r++) acc[r] += sfeat[r][k] * wv;
    }
#pragma unroll
    for (int k = 0; k < TPROJv; k++) {
        float wv = W_ntime[c * TPROJv + k];
#pragma unroll
        for (int r = 0; r < NR; r++) acc[r] += stemb[r][k] * wv;
    }
#pragma unroll
    for (int r = 0; r < NR; r++) sx[r][c] = fmaxf(acc[r], 0.0f);

    {
        const int c2 = tid & 127, half = tid >> 7;
        float e[NR];
#pragma unroll
        for (int r = 0; r < NR; r++) e[r] = 0.0f;
#pragma unroll
        for (int k = 0; k < TFv; k++) {
            float wv = W_etf[c2 * (2 * TFv) + half * TFv + k];
#pragma unroll
            for (int r = 0; r < NR; r++) e[r] += sfeat[r][k] * wv;
        }
#pragma unroll
        for (int k = 0; k < TPROJv; k++) {
            float wv = W_etime[c2 * (2 * TPROJv) + half * TPROJv + k];
#pragma unroll
            for (int r = 0; r < NR; r++) e[r] += stemb[r][k] * wv;
        }
        float* dst = half ? g_eR : g_eL;
#pragma unroll
        for (int r = 0; r < NR; r++) dst[(row0 + r) * CZv + c2] = e[r];
    }
    __syncthreads();

    float h[NR];
#pragma unroll
    for (int r = 0; r < NR; r++) h[r] = b_n1[c];
    {
        const float4* W1r = (const float4*)(W_n1 + c * CSv);
#pragma unroll 4
        for (int q = 0; q < CSv / 4; q++) {
            float4 wv = W1r[q];
#pragma unroll
            for (int r = 0; r < NR; r++) {
                float4 xv = *(const float4*)&sx[r][q * 4];
                h[r] += xv.x * wv.x + xv.y * wv.y + xv.z * wv.z + xv.w * wv.w;
            }
        }
    }
    __syncthreads();
#pragma unroll
    for (int r = 0; r < NR; r++) sx[r][c] = fmaxf(h[r], 0.0f);
    __syncthreads();

    float o[NR];
#pragma unroll
    for (int r = 0; r < NR; r++) o[r] = b_n2[c];
    {
        const float4* W2r = (const float4*)(W_n2 + c * CSv);
#pragma unroll 4
        for (int q = 0; q < CSv / 4; q++) {
            float4 wv = W2r[q];
#pragma unroll
            for (int r = 0; r < NR; r++) {
                float4 xv = *(const float4*)&sx[r][q * 4];
                o[r] += xv.x * wv.x + xv.y * wv.y + xv.z * wv.z + xv.w * wv.w;
            }
        }
    }
    __syncthreads();
#pragma unroll
    for (int r = 0; r < NR; r++) sx[r][c] = o[r];
    __syncthreads();

    {
        const int w = tid >> 5, l = tid & 31;
        float v[8];
#pragma unroll
        for (int g = 0; g < 8; g++) v[g] = sx[w][g * 32 + l];
        float s = 0.0f;
#pragma unroll
        for (int g = 0; g < 8; g++) s += v[g];
#pragma unroll
        for (int off = 16; off > 0; off >>= 1) s += __shfl_xor_sync(0xffffffffu, s, off);
        float mean = s * (1.0f / 256.0f);
        float sq = 0.0f;
#pragma unroll
        for (int g = 0; g < 8; g++) { float d = v[g] - mean; sq += d * d; }
#pragma unroll
        for (int off = 16; off > 0; off >>= 1) sq += __shfl_xor_sync(0xffffffffu, sq, off);
        float rstd = rsqrtf(sq * (1.0f / 256.0f) + LN_EPS);
        const int row = row0 + w;
#pragma unroll
        for (int g = 0; g < 8; g++) {
            int cc = g * 32 + l;
            out_seq[row * CSv + cc] = (v[g] - mean) * rstd * g_n[cc] + be_n[cc];
        }
    }
}

// ---------------------------------------------------------------------------
// Edge kernel v4: warp-autonomous, fp16 X and fp16 H, occupancy 3.
// GEMM1 runs in two n-halves (acc1 = 32 regs), each half transformed
// immediately into A-fragments for GEMM2.
// ---------------------------------------------------------------------------
#define WSTR 68
#define XH_W 0
#define WS_W (128 * WSTR)
#define REL_W (2 * 128 * WSTR)
#define EDGE_SMEM_U32 (REL_W + 128 + 8)
#define EDGE_SMEM_BYTES (EDGE_SMEM_U32 * 4)

__global__ __launch_bounds__(256, 3) void edge_kernel(
    const int* __restrict__ seq_idx,
    const float* __restrict__ b_e1, const float* __restrict__ b_e2,
    const float* __restrict__ g_e, const float* __restrict__ be_e,
    float* __restrict__ out_edge) {
    extern __shared__ uint32_t smw[];
    uint32_t* Xh = smw + XH_W;
    uint32_t* Ws = smw + WS_W;
    int* s_rel = (int*)(smw + REL_W);

    const int tid = threadIdx.x, w = tid >> 5, l = tid & 31;
    const int g = l >> 2, tig = l & 3;
    const int m0 = w * 16;
    const int bid = blockIdx.x;
    const int jt = bid % 3, i = (bid / 3) % NN, b = bid / (3 * NN);
    const int j0 = jt * 128;

    const uint32_t sb = smem_u32(smw);
    const int l16 = l & 15, lhi = l >> 4;
    const uint32_t aAddr = sb + ((m0 + l16) * WSTR + lhi * 4) * 4;       // X (Xh)
    const int nB = (l & 7) + (lhi << 3);
    const int kofB = ((l >> 3) & 1) << 2;
    const uint32_t bAddr1 = sb + (WS_W + nB * WSTR + kofB) * 4;          // W1 (Ws)
    const uint32_t bAddr2 = sb + (nB * WSTR + kofB) * 4;                 // W2 (Xh)

    if (tid < 128) {
        int rel = seq_idx[b * NN + i] - seq_idx[b * NN + j0 + tid] + 1000;
        s_rel[tid] = min(max(rel, 0), 2047);
    }
    {   // stage W1 into Ws (cooperative)
        const float4* Wsrc = (const float4*)g_W1f;
        for (int m = tid; m < 2048; m += 256) {
            int n = m >> 4, c4 = m & 15;
            *(float4*)&Ws[n * WSTR + c4 * 4] = Wsrc[m];
        }
    }
    __syncthreads();   // sync #1: rel + W1 visible

    // ---- X build (own 16 rows), single fp16 ----
    {
        const float4 Lv = ((const float4*)(g_eL + (size_t)(b * NN + i) * CZv))[l];
        unsigned long long* Xh64 = (unsigned long long*)Xh;
#pragma unroll 4
        for (int it = 0; it < 16; it++) {
            const int r = m0 + it;
            float4 tv = ((const float4*)(g_table + (size_t)s_rel[r] * CZv))[l];
            float4 rv = ((const float4*)(g_eR + (size_t)(b * NN + j0 + r) * CZv))[l];
            uint32_t h01 = packh2(fmaxf(tv.x + Lv.x + rv.x, 0.0f),
                                  fmaxf(tv.y + Lv.y + rv.y, 0.0f));
            uint32_t h23 = packh2(fmaxf(tv.z + Lv.z + rv.z, 0.0f),
                                  fmaxf(tv.w + Lv.w + rv.w, 0.0f));
            Xh64[r * 34 + l] = ((unsigned long long)h23 << 32) | h01;
        }
    }
    __syncwarp();

    // ---- GEMM1 + transform, two n-halves: Ah[q] = fp16 A-frag of H ----
    uint32_t Ah[8][4];
#pragma unroll
    for (int h = 0; h < 2; h++) {
        float acc1[8][4];
#pragma unroll
        for (int nt = 0; nt < 8; nt++)
#pragma unroll
            for (int e = 0; e < 4; e++) acc1[nt][e] = 0.0f;
#pragma unroll
        for (int kk = 0; kk < 8; kk++) {
            const uint32_t kb = kk * 32;
            uint32_t ah[4];
            ldsm_x4(ah[0], ah[1], ah[2], ah[3], aAddr + kb);
#pragma unroll
            for (int p = 0; p < 4; p++) {
                uint32_t bf[4];
                ldsm_x4(bf[0], bf[1], bf[2], bf[3],
                        bAddr1 + (h * 4 + p) * (16 * WSTR * 4) + kb);
                mma16816(acc1[2 * p], ah[0], ah[1], ah[2], ah[3], bf[0], bf[1]);
                mma16816(acc1[2 * p + 1], ah[0], ah[1], ah[2], ah[3], bf[2], bf[3]);
            }
        }
#pragma unroll
        for (int p = 0; p < 4; p++) {
            const int q = h * 4 + p;
            const int c0 = 16 * q + 2 * tig;
            const int c1 = c0 + 8;
            float b00 = __ldg(b_e1 + c0), b01 = __ldg(b_e1 + c0 + 1);
            float b10 = __ldg(b_e1 + c1), b11 = __ldg(b_e1 + c1 + 1);
            Ah[q][0] = packh2(fmaxf(acc1[2 * p][0] + b00, 0.0f),
                              fmaxf(acc1[2 * p][1] + b01, 0.0f));
            Ah[q][1] = packh2(fmaxf(acc1[2 * p][2] + b00, 0.0f),
                              fmaxf(acc1[2 * p][3] + b01, 0.0f));
            Ah[q][2] = packh2(fmaxf(acc1[2 * p + 1][0] + b10, 0.0f),
                              fmaxf(acc1[2 * p + 1][1] + b11, 0.0f));
            Ah[q][3] = packh2(fmaxf(acc1[2 * p + 1][2] + b10, 0.0f),
                              fmaxf(acc1[2 * p + 1][3] + b11, 0.0f));
        }
    }

    // ---- Stage W2 rows m0..m0+15 into OWN Xh slice (X dead for this warp) ----
    {
        const float4* Wsrc = (const float4*)g_W2f;
#pragma unroll
        for (int it = 0; it < 8; it++) {
            int idx = it * 32 + l;
            int rn = m0 + (idx >> 4), c4 = idx & 15;
            *(float4*)&Xh[rn * WSTR + c4 * 4] = Wsrc[rn * 16 + c4];
        }
    }
    __syncthreads();   // sync #2: all W2 slices staged

    // ---- GEMM2 in two 64-col halves (A = Ah regs, B = W2 in Xh) ----
    float sumA = 0.0f, sqA = 0.0f, sumB = 0.0f, sqB = 0.0f;
    float* E0 = (float*)(Ws + m0 * WSTR);   // own W1 slice (dead): park half0
    const float* ge = g_e;
    const float* bee = be_e;

    float acc2[8][4];
#pragma unroll
    for (int h = 0; h < 2; h++) {
#pragma unroll
        for (int nt = 0; nt < 8; nt++)
#pragma unroll
            for (int e = 0; e < 4; e++) acc2[nt][e] = 0.0f;
#pragma unroll
        for (int kk = 0; kk < 8; kk++) {
            const uint32_t kb = kk * 32;
#pragma unroll
            for (int p = 0; p < 4; p++) {
                uint32_t bf[4];
                ldsm_x4(bf[0], bf[1], bf[2], bf[3],
                        bAddr2 + (h * 4 + p) * (16 * WSTR * 4) + kb);
                mma16816(acc2[2 * p], Ah[kk][0], Ah[kk][1], Ah[kk][2], Ah[kk][3],
                         bf[0], bf[1]);
                mma16816(acc2[2 * p + 1], Ah[kk][0], Ah[kk][1], Ah[kk][2], Ah[kk][3],
                         bf[2], bf[3]);
            }
        }
#pragma unroll
        for (int nt = 0; nt < 8; nt++) {
            const int col = h * 64 + 8 * nt + 2 * tig;
            float bb0 = __ldg(b_e2 + col), bb1 = __ldg(b_e2 + col + 1);
            float v0 = acc2[nt][0] + bb0, v1 = acc2[nt][1] + bb1;
            float v2 = acc2[nt][2] + bb0, v3 = acc2[nt][3] + bb1;
            sumA += v0 + v1; sqA += v0 * v0 + v1 * v1;
            sumB += v2 + v3; sqB += v2 * v2 + v3 * v3;
            if (h == 0) {
                *(float2*)&E0[g * WSTR + 8 * nt + 2 * tig] = make_float2(v0, v1);
                *(float2*)&E0[(g + 8) * WSTR + 8 * nt + 2 * tig] = make_float2(v2, v3);
            } else {
                acc2[nt][0] = v0; acc2[nt][1] = v1;
                acc2[nt][2] = v2; acc2[nt][3] = v3;
            }
        }
    }

    // ---- LN stats over the 4-lane quad ----
#pragma unroll
    for (int off = 1; off <= 2; off <<= 1) {
        sumA += __shfl_xor_sync(0xffffffffu, sumA, off);
        sqA += __shfl_xor_sync(0xffffffffu, sqA, off);
        sumB += __shfl_xor_sync(0xffffffffu, sumB, off);
        sqB += __shfl_xor_sync(0xffffffffu, sqB, off);
    }
    const float mA = sumA * (1.0f / 128.0f);
    const float rA = rsqrtf(fmaxf(sqA * (1.0f / 128.0f) - mA * mA, 0.0f) + LN_EPS);
    const float mB = sumB * (1.0f / 128.0f);
    const float rB = rsqrtf(fmaxf(sqB * (1.0f / 128.0f) - mB * mB, 0.0f) + LN_EPS);

    const size_t rowbase = ((size_t)(b * NN + i) * NN + (j0 + m0));

    // half1 (cols 64..127) directly from registers
    {
        float* dstg = out_edge + (rowbase + g) * CZv;
        float* dstg8 = out_edge + (rowbase + g + 8) * CZv;
#pragma unroll
        for (int nt = 0; nt < 8; nt++) {
            const int col = 64 + 8 * nt + 2 * tig;
            float ge0 = __ldg(ge + col), ge1 = __ldg(ge + col + 1);
            float be0 = __ldg(bee + col), be1 = __ldg(bee + col + 1);
            *(float2*)&dstg[col] = make_float2(
                (acc2[nt][0] - mA) * rA * ge0 + be0,
                (acc2[nt][1] - mA) * rA * ge1 + be1);
            *(float2*)&dstg8[col] = make_float2(
                (acc2[nt][2] - mB) * rB * ge0 + be0,
                (acc2[nt][3] - mB) * rB * ge1 + be1);
        }
    }
    __syncwarp();

    // half0 (cols 0..63) coalesced from E0 with shuffled stats
    {
        const float ge0 = ge[l], ge1 = ge[32 + l];
        const float be0 = bee[l], be1 = bee[32 + l];
#pragma unroll 2
        for (int r = 0; r < 16; r++) {
            const int src = 4 * (r & 7);
            float m1 = __shfl_sync(0xffffffffu, mA, src);
            float m2 = __shfl_sync(0xffffffffu, mB, src);
            float r1 = __shfl_sync(0xffffffffu, rA, src);
            float r2 = __shfl_sync(0xffffffffu, rB, src);
            float mean = (r < 8) ? m1 : m2;
            float rstd = (r < 8) ? r1 : r2;
            float v0 = E0[r * WSTR + l];
            float v1 = E0[r * WSTR + 32 + l];
            float* dst = out_edge + (rowbase + r) * CZv;
            dst[l] = (v0 - mean) * rstd * ge0 + be0;
            dst[32 + l] = (v1 - mean) * rstd * ge1 + be1;
        }
    }
}

// ===========================================================================
extern "C" void kernel_launch(void* const* d_in, const int* in_sizes, int n_in,
                              void* d_out, int out_size) {
    const int* seq_idx = (const int*)d_in[0];
    const float* seq_feat = (const float*)d_in[1];
    const float* timestep = (const float*)d_in[2];
    const float* frame_mask = (const float*)d_in[3];
    const float* W_npos = (const float*)d_in[4];
    const float* b_npos = (const float*)d_in[5];
    const float* W_ntf = (const float*)d_in[6];
    const float* b_ntf = (const float*)d_in[7];
    const float* W_ntime = (const float*)d_in[8];
    const float* b_ntime = (const float*)d_in[9];
    const float* W_n1 = (const float*)d_in[10];
    const float* b_n1 = (const float*)d_in[11];
    const float* W_n2 = (const float*)d_in[12];
    const float* b_n2 = (const float*)d_in[13];
    const float* g_n = (const float*)d_in[14];
    const float* be_n = (const float*)d_in[15];
    const float* W_epos = (const float*)d_in[16];
    const float* b_epos = (const float*)d_in[17];
    const float* W_etf = (const float*)d_in[18];
    const float* b_etf = (const float*)d_in[19];
    const float* W_etime = (const float*)d_in[20];
    const float* b_etime = (const float*)d_in[21];
    const float* W_e1 = (const float*)d_in[22];
    const float* b_e1 = (const float*)d_in[23];
    const float* W_e2 = (const float*)d_in[24];
    const float* b_e2 = (const float*)d_in[25];
    const float* g_e = (const float*)d_in[26];
    const float* be_e = (const float*)d_in[27];

    float* out = (float*)d_out;
    float* out_seq = out;
    float* out_edge = out + NB * NN * CSv;

    static int configured = 0;
    if (!configured) {
        cudaFuncSetAttribute(edge_kernel, cudaFuncAttributeMaxDynamicSharedMemorySize,
                             EDGE_SMEM_BYTES);
        configured = 1;
    }

    setup_kernel<<<TBLK + NODEB + 64, 256>>>(
        seq_idx, seq_feat, timestep, frame_mask,
        W_npos, b_npos, W_ntf, b_ntf, W_ntime, b_ntime,
        W_n1, b_n1, W_n2, b_n2, g_n, be_n,
        W_epos, b_epos, b_etf, b_etime, W_etf, W_etime,
        W_e1, W_e2, out_seq);
    edge_kernel<<<NB * NN * 3, 256, EDGE_SMEM_BYTES>>>(seq_idx, b_e1, b_e2,
                                                       g_e, be_e, out_edge);
}

// round 15
// speedup vs baseline: 1.0973x; 1.0973x over previous
#include <cuda_runtime.h>
#include <cuda_fp16.h>
#include <cstdint>

#define NB 2
#define NN 384
#define TFv 22
#define POSv 32
#define TPROJv 33
#define CSv 256
#define CZv 128
#define LN_EPS 1e-5f
#define PI_F 3.14159265358979323846f

__device__ float g_table[2048 * CZv];
__device__ float g_eL[NB * NN * CZv];
__device__ float g_eR[NB * NN * CZv];
__device__ __half g_W1f[CZv * CZv], g_W2f[CZv * CZv];

// ---------------------------------------------------------------------------
// helpers
// ---------------------------------------------------------------------------
__device__ __forceinline__ uint32_t smem_u32(const void* p) {
    uint32_t a;
    asm("{ .reg .u64 t; cvta.to.shared.u64 t, %1; cvt.u32.u64 %0, t; }"
        : "=r"(a) : "l"(p));
    return a;
}
__device__ __forceinline__ uint32_t packh2(float r0, float r1) {
    __half2 v = __floats2half2_rn(r0, r1);
    return *reinterpret_cast<uint32_t*>(&v);
}
__device__ __forceinline__ void mma16816(float* c, uint32_t a0, uint32_t a1,
                                         uint32_t a2, uint32_t a3,
                                         uint32_t b0, uint32_t b1) {
    asm volatile(
        "mma.sync.aligned.m16n8k16.row.col.f32.f16.f16.f32 "
        "{%0,%1,%2,%3}, {%4,%5,%6,%7}, {%8,%9}, {%0,%1,%2,%3};"
        : "+f"(c[0]), "+f"(c[1]), "+f"(c[2]), "+f"(c[3])
        : "r"(a0), "r"(a1), "r"(a2), "r"(a3), "r"(b0), "r"(b1));
}
__device__ __forceinline__ void ldsm_x4(uint32_t& r0, uint32_t& r1,
                                        uint32_t& r2, uint32_t& r3, uint32_t addr) {
    asm volatile("ldmatrix.sync.aligned.m8n8.x4.shared.b16 {%0,%1,%2,%3}, [%4];"
                 : "=r"(r0), "=r"(r1), "=r"(r2), "=r"(r3) : "r"(addr));
}

// ---------------------------------------------------------------------------
// Fused setup kernel (unchanged — correctness proven).
// ---------------------------------------------------------------------------
#define NR 8
#define TBLK 1024
#define NODEB (NB * NN / NR)   // 96

__global__ __launch_bounds__(256) void setup_kernel(
    const int* __restrict__ seq_idx, const float* __restrict__ seq_feat,
    const float* __restrict__ timestep, const float* __restrict__ frame_mask,
    const float* __restrict__ W_npos, const float* __restrict__ b_npos,
    const float* __restrict__ W_ntf, const float* __restrict__ b_ntf,
    const float* __restrict__ W_ntime, const float* __restrict__ b_ntime,
    const float* __restrict__ W_n1, const float* __restrict__ b_n1,
    const float* __restrict__ W_n2, const float* __restrict__ b_n2,
    const float* __restrict__ g_n, const float* __restrict__ be_n,
    const float* __restrict__ W_epos, const float* __restrict__ b_epos,
    const float* __restrict__ b_etf, const float* __restrict__ b_etime,
    const float* __restrict__ W_etf, const float* __restrict__ W_etime,
    const float* __restrict__ W_e1, const float* __restrict__ W_e2,
    float* __restrict__ out_seq) {
    __shared__ float su[4352];
    const int tid = threadIdx.x;
    const int bid = blockIdx.x;

    if (bid < TBLK) {
        float* sWe = su;
        float* emb = su + 4224;
        const int half = tid >> 7, c = tid & 127;
        for (int m = tid; m < CZv * POSv; m += 256)
            sWe[(m >> 5) * 33 + (m & 31)] = W_epos[m];
        const int relv = bid * 2 + half - 1000;
        if (c < 16) {
            float p = powf(2056.0f, (float)c * (1.0f / 16.0f));
            float ang = ((float)relv * PI_F) / p;
            emb[half * 32 + c] = sinf(ang);
            emb[half * 32 + c + 16] = cosf(ang);
        }
        __syncthreads();
        float acc = b_epos[c] + b_etf[c] + b_etime[c];
#pragma unroll
        for (int k = 0; k < POSv; k++) acc += emb[half * 32 + k] * sWe[c * 33 + k];
        g_table[(bid * 2 + half) * CZv + c] = acc;
        return;
    }
    if (bid >= TBLK + NODEB) {
        int t = (bid - TBLK - NODEB) * 256 + tid;
        g_W1f[t] = __float2half_rn(W_e1[t]);
        g_W2f[t] = __float2half_rn(W_e2[t]);
        return;
    }

    float (*spemb)[POSv] = (float(*)[POSv])su;
    float (*stemb)[36] = (float(*)[36])(su + 256);
    float (*sfeat)[24] = (float(*)[24])(su + 544);
    float (*sx)[CSv] = (float(*)[CSv])(su + 736);
    const int row0 = (bid - TBLK) * NR;

    {
        const int r = tid >> 5, j = tid & 31;
        const int row = row0 + r;
        const int b = row / NN;
        if (j < TFv) sfeat[r][j] = seq_feat[row * TFv + j];
        if (j < 16) {
            float p = powf(2056.0f, (float)j * (1.0f / 16.0f));
            float ang = ((float)seq_idx[row] * PI_F) / p;
            spemb[r][j] = sinf(ang);
            spemb[r][j + 16] = cosf(ang);
            float fm = frame_mask[row];
            float tt = timestep[b] * fm;
            float fr = expf(-0.6140226914650789f * (float)j);
            float a2 = tt * fr;
            stemb[r][j] = sinf(a2);
            stemb[r][j + 16] = cosf(a2);
            if (j == 0) stemb[r][32] = fm;
        }
    }
    __syncthreads();

    const int c = tid;
    float acc[NR];
    {
        float base = b_npos[c] + b_ntf[c] + b_ntime[c];
#pragma unroll
        for (int r = 0; r < NR; r++) acc[r] = base;
    }
#pragma unroll
    for (int k = 0; k < POSv; k++) {
        float wv = W_npos[c * POSv + k];
#pragma unroll
        for (int r = 0; r < NR; r++) acc[r] += spemb[r][k] * wv;
    }
#pragma unroll
    for (int k = 0; k < TFv; k++) {
        float wv = W_ntf[c * TFv + k];
#pragma unroll
        for (int r = 0; r < NR; r++) acc[r] += sfeat[r][k] * wv;
    }
#pragma unroll
    for (int k = 0; k < TPROJv; k++) {
        float wv = W_ntime[c * TPROJv + k];
#pragma unroll
        for (int r = 0; r < NR; r++) acc[r] += stemb[r][k] * wv;
    }
#pragma unroll
    for (int r = 0; r < NR; r++) sx[r][c] = fmaxf(acc[r], 0.0f);

    {
        const int c2 = tid & 127, half = tid >> 7;
        float e[NR];
#pragma unroll
        for (int r = 0; r < NR; r++) e[r] = 0.0f;
#pragma unroll
        for (int k = 0; k < TFv; k++) {
            float wv = W_etf[c2 * (2 * TFv) + half * TFv + k];
#pragma unroll
            for (int r = 0; r < NR; r++) e[r] += sfeat[r][k] * wv;
        }
#pragma unroll
        for (int k = 0; k < TPROJv; k++) {
            float wv = W_etime[c2 * (2 * TPROJv) + half * TPROJv + k];
#pragma unroll
            for (int r = 0; r < NR; r++) e[r] += stemb[r][k] * wv;
        }
        float* dst = half ? g_eR : g_eL;
#pragma unroll
        for (int r = 0; r < NR; r++) dst[(row0 + r) * CZv + c2] = e[r];
    }
    __syncthreads();

    float h[NR];
#pragma unroll
    for (int r = 0; r < NR; r++) h[r] = b_n1[c];
    {
        const float4* W1r = (const float4*)(W_n1 + c * CSv);
#pragma unroll 4
        for (int q = 0; q < CSv / 4; q++) {
            float4 wv = W1r[q];
#pragma unroll
            for (int r = 0; r < NR; r++) {
                float4 xv = *(const float4*)&sx[r][q * 4];
                h[r] += xv.x * wv.x + xv.y * wv.y + xv.z * wv.z + xv.w * wv.w;
            }
        }
    }
    __syncthreads();
#pragma unroll
    for (int r = 0; r < NR; r++) sx[r][c] = fmaxf(h[r], 0.0f);
    __syncthreads();

    float o[NR];
#pragma unroll
    for (int r = 0; r < NR; r++) o[r] = b_n2[c];
    {
        const float4* W2r = (const float4*)(W_n2 + c * CSv);
#pragma unroll 4
        for (int q = 0; q < CSv / 4; q++) {
            float4 wv = W2r[q];
#pragma unroll
            for (int r = 0; r < NR; r++) {
                float4 xv = *(const float4*)&sx[r][q * 4];
                o[r] += xv.x * wv.x + xv.y * wv.y + xv.z * wv.z + xv.w * wv.w;
            }
        }
    }
    __syncthreads();
#pragma unroll
    for (int r = 0; r < NR; r++) sx[r][c] = o[r];
    __syncthreads();

    {
        const int w = tid >> 5, l = tid & 31;
        float v[8];
#pragma unroll
        for (int g = 0; g < 8; g++) v[g] = sx[w][g * 32 + l];
        float s = 0.0f;
#pragma unroll
        for (int g = 0; g < 8; g++) s += v[g];
#pragma unroll
        for (int off = 16; off > 0; off >>= 1) s += __shfl_xor_sync(0xffffffffu, s, off);
        float mean = s * (1.0f / 256.0f);
        float sq = 0.0f;
#pragma unroll
        for (int g = 0; g < 8; g++) { float d = v[g] - mean; sq += d * d; }
#pragma unroll
        for (int off = 16; off > 0; off >>= 1) sq += __shfl_xor_sync(0xffffffffu, sq, off);
        float rstd = rsqrtf(sq * (1.0f / 256.0f) + LN_EPS);
        const int row = row0 + w;
#pragma unroll
        for (int g = 0; g < 8; g++) {
            int cc = g * 32 + l;
            out_seq[row * CSv + cc] = (v[g] - mean) * rstd * g_n[cc] + be_n[cc];
        }
    }
}

// ---------------------------------------------------------------------------
// Edge kernel v5: R13 structure (occ 2, single-pass GEMM1, W2 reg prefetch)
// with single-fp16 H in GEMM2 (half the MMAs, Ah only).
// ---------------------------------------------------------------------------
#define WSTR 68
#define XH_W 0
#define WS_W (128 * WSTR)
#define REL_W (2 * 128 * WSTR)
#define EDGE_SMEM_U32 (REL_W + 128 + 8)
#define EDGE_SMEM_BYTES (EDGE_SMEM_U32 * 4)

__global__ __launch_bounds__(256, 2) void edge_kernel(
    const int* __restrict__ seq_idx,
    const float* __restrict__ b_e1, const float* __restrict__ b_e2,
    const float* __restrict__ g_e, const float* __restrict__ be_e,
    float* __restrict__ out_edge) {
    extern __shared__ uint32_t smw[];
    uint32_t* Xh = smw + XH_W;
    uint32_t* Ws = smw + WS_W;
    int* s_rel = (int*)(smw + REL_W);

    const int tid = threadIdx.x, w = tid >> 5, l = tid & 31;
    const int g = l >> 2, tig = l & 3;
    const int m0 = w * 16;
    const int bid = blockIdx.x;
    const int jt = bid % 3, i = (bid / 3) % NN, b = bid / (3 * NN);
    const int j0 = jt * 128;

    const uint32_t sb = smem_u32(smw);
    const int l16 = l & 15, lhi = l >> 4;
    const uint32_t aAddr = sb + ((m0 + l16) * WSTR + lhi * 4) * 4;       // X (Xh)
    const int nB = (l & 7) + (lhi << 3);
    const int kofB = ((l >> 3) & 1) << 2;
    const uint32_t bAddr1 = sb + (WS_W + nB * WSTR + kofB) * 4;          // W1 (Ws)
    const uint32_t bAddr2 = sb + (nB * WSTR + kofB) * 4;                 // W2 (Xh)

    if (tid < 128) {
        int rel = seq_idx[b * NN + i] - seq_idx[b * NN + j0 + tid] + 1000;
        s_rel[tid] = min(max(rel, 0), 2047);
    }
    {   // stage W1 into Ws (cooperative)
        const float4* Wsrc = (const float4*)g_W1f;
        for (int m = tid; m < 2048; m += 256) {
            int n = m >> 4, c4 = m & 15;
            *(float4*)&Ws[n * WSTR + c4 * 4] = Wsrc[m];
        }
    }
    __syncthreads();   // sync #1: rel + W1 visible

    // ---- X build (own 16 rows), single fp16 ----
    {
        const float4 Lv = ((const float4*)(g_eL + (size_t)(b * NN + i) * CZv))[l];
        unsigned long long* Xh64 = (unsigned long long*)Xh;
#pragma unroll 4
        for (int it = 0; it < 16; it++) {
            const int r = m0 + it;
            float4 tv = ((const float4*)(g_table + (size_t)s_rel[r] * CZv))[l];
            float4 rv = ((const float4*)(g_eR + (size_t)(b * NN + j0 + r) * CZv))[l];
            uint32_t h01 = packh2(fmaxf(tv.x + Lv.x + rv.x, 0.0f),
                                  fmaxf(tv.y + Lv.y + rv.y, 0.0f));
            uint32_t h23 = packh2(fmaxf(tv.z + Lv.z + rv.z, 0.0f),
                                  fmaxf(tv.w + Lv.w + rv.w, 0.0f));
            Xh64[r * 34 + l] = ((unsigned long long)h23 << 32) | h01;
        }
    }
    // Prefetch this warp's W2 slice into registers (hidden under GEMM1).
    float4 w2r[8];
    {
        const float4* Wsrc = (const float4*)g_W2f;
#pragma unroll
        for (int it = 0; it < 8; it++) {
            int idx = it * 32 + l;
            w2r[it] = Wsrc[(m0 + (idx >> 4)) * 16 + (idx & 15)];
        }
    }
    __syncwarp();

    // ---- GEMM1: acc1[16][4] = X(16 x k128, fp16) @ W1^T ----
    float acc1[16][4];
#pragma unroll
    for (int nt = 0; nt < 16; nt++)
#pragma unroll
        for (int e = 0; e < 4; e++) acc1[nt][e] = 0.0f;
#pragma unroll
    for (int kk = 0; kk < 8; kk++) {
        const uint32_t kb = kk * 32;
        uint32_t ah[4];
        ldsm_x4(ah[0], ah[1], ah[2], ah[3], aAddr + kb);
#pragma unroll
        for (int p = 0; p < 8; p++) {
            uint32_t bf[4];
            ldsm_x4(bf[0], bf[1], bf[2], bf[3], bAddr1 + p * (16 * WSTR * 4) + kb);
            mma16816(acc1[2 * p], ah[0], ah[1], ah[2], ah[3], bf[0], bf[1]);
            mma16816(acc1[2 * p + 1], ah[0], ah[1], ah[2], ah[3], bf[2], bf[3]);
        }
    }

    // ---- Transform: H = relu(acc1 + b_e1) -> single-fp16 A-fragments ----
    uint32_t Ah[8][4];
#pragma unroll
    for (int q = 0; q < 8; q++) {
        const int c0 = 16 * q + 2 * tig;
        const int c1 = c0 + 8;
        float b00 = __ldg(b_e1 + c0), b01 = __ldg(b_e1 + c0 + 1);
        float b10 = __ldg(b_e1 + c1), b11 = __ldg(b_e1 + c1 + 1);
        Ah[q][0] = packh2(fmaxf(acc1[2 * q][0] + b00, 0.0f),
                          fmaxf(acc1[2 * q][1] + b01, 0.0f));
        Ah[q][1] = packh2(fmaxf(acc1[2 * q][2] + b00, 0.0f),
                          fmaxf(acc1[2 * q][3] + b01, 0.0f));
        Ah[q][2] = packh2(fmaxf(acc1[2 * q + 1][0] + b10, 0.0f),
                          fmaxf(acc1[2 * q + 1][1] + b11, 0.0f));
        Ah[q][3] = packh2(fmaxf(acc1[2 * q + 1][2] + b10, 0.0f),
                          fmaxf(acc1[2 * q + 1][3] + b11, 0.0f));
    }

    // ---- Store prefetched W2 slice into OWN Xh rows (X dead for this warp) ----
    {
#pragma unroll
        for (int it = 0; it < 8; it++) {
            int idx = it * 32 + l;
            int rn = m0 + (idx >> 4), c4 = idx & 15;
            *(float4*)&Xh[rn * WSTR + c4 * 4] = w2r[it];
        }
    }
    __syncthreads();   // sync #2: all W2 slices staged

    // ---- GEMM2 in two 64-col halves (A = Ah regs, fp16; B = W2 in Xh) ----
    float sumA = 0.0f, sqA = 0.0f, sumB = 0.0f, sqB = 0.0f;
    float* E0 = (float*)(Ws + m0 * WSTR);   // own W1 slice (dead): park half0
    const float* ge = g_e;
    const float* bee = be_e;

    float acc2[8][4];
#pragma unroll
    for (int h = 0; h < 2; h++) {
#pragma unroll
        for (int nt = 0; nt < 8; nt++)
#pragma unroll
            for (int e = 0; e < 4; e++) acc2[nt][e] = 0.0f;
#pragma unroll
        for (int kk = 0; kk < 8; kk++) {
            const uint32_t kb = kk * 32;
#pragma unroll
            for (int p = 0; p < 4; p++) {
                uint32_t bf[4];
                ldsm_x4(bf[0], bf[1], bf[2], bf[3],
                        bAddr2 + (h * 4 + p) * (16 * WSTR * 4) + kb);
                mma16816(acc2[2 * p], Ah[kk][0], Ah[kk][1], Ah[kk][2], Ah[kk][3],
                         bf[0], bf[1]);
                mma16816(acc2[2 * p + 1], Ah[kk][0], Ah[kk][1], Ah[kk][2], Ah[kk][3],
                         bf[2], bf[3]);
            }
        }
#pragma unroll
        for (int nt = 0; nt < 8; nt++) {
            const int col = h * 64 + 8 * nt + 2 * tig;
            float bb0 = __ldg(b_e2 + col), bb1 = __ldg(b_e2 + col + 1);
            float v0 = acc2[nt][0] + bb0, v1 = acc2[nt][1] + bb1;
            float v2 = acc2[nt][2] + bb0, v3 = acc2[nt][3] + bb1;
            sumA += v0 + v1; sqA += v0 * v0 + v1 * v1;
            sumB += v2 + v3; sqB += v2 * v2 + v3 * v3;
            if (h == 0) {
                *(float2*)&E0[g * WSTR + 8 * nt + 2 * tig] = make_float2(v0, v1);
                *(float2*)&E0[(g + 8) * WSTR + 8 * nt + 2 * tig] = make_float2(v2, v3);
            } else {
                acc2[nt][0] = v0; acc2[nt][1] = v1;
                acc2[nt][2] = v2; acc2[nt][3] = v3;
            }
        }
    }

    // ---- LN stats over the 4-lane quad ----
#pragma unroll
    for (int off = 1; off <= 2; off <<= 1) {
        sumA += __shfl_xor_sync(0xffffffffu, sumA, off);
        sqA += __shfl_xor_sync(0xffffffffu, sqA, off);
        sumB += __shfl_xor_sync(0xffffffffu, sumB, off);
        sqB += __shfl_xor_sync(0xffffffffu, sqB, off);
    }
    const float mA = sumA * (1.0f / 128.0f);
    const float rA = rsqrtf(fmaxf(sqA * (1.0f / 128.0f) - mA * mA, 0.0f) + LN_EPS);
    const float mB = sumB * (1.0f / 128.0f);
    const float rB = rsqrtf(fmaxf(sqB * (1.0f / 128.0f) - mB * mB, 0.0f) + LN_EPS);

    const size_t rowbase = ((size_t)(b * NN + i) * NN + (j0 + m0));

    // half1 (cols 64..127) directly from registers
    {
        float* dstg = out_edge + (rowbase + g) * CZv;
        float* dstg8 = out_edge + (rowbase + g + 8) * CZv;
#pragma unroll
        for (int nt = 0; nt < 8; nt++) {
            const int col = 64 + 8 * nt + 2 * tig;
            float ge0 = __ldg(ge + col), ge1 = __ldg(ge + col + 1);
            float be0 = __ldg(bee + col), be1 = __ldg(bee + col + 1);
            *(float2*)&dstg[col] = make_float2(
                (acc2[nt][0] - mA) * rA * ge0 + be0,
                (acc2[nt][1] - mA) * rA * ge1 + be1);
            *(float2*)&dstg8[col] = make_float2(
                (acc2[nt][2] - mB) * rB * ge0 + be0,
                (acc2[nt][3] - mB) * rB * ge1 + be1);
        }
    }
    __syncwarp();

    // half0 (cols 0..63) coalesced from E0 with shuffled stats
    {
        const float ge0 = ge[l], ge1 = ge[32 + l];
        const float be0 = bee[l], be1 = bee[32 + l];
#pragma unroll 2
        for (int r = 0; r < 16; r++) {
            const int src = 4 * (r & 7);
            float m1 = __shfl_sync(0xffffffffu, mA, src);
            float m2 = __shfl_sync(0xffffffffu, mB, src);
            float r1 = __shfl_sync(0xffffffffu, rA, src);
            float r2 = __shfl_sync(0xffffffffu, rB, src);
            float mean = (r < 8) ? m1 : m2;
            float rstd = (r < 8) ? r1 : r2;
            float v0 = E0[r * WSTR + l];
            float v1 = E0[r * WSTR + 32 + l];
            float* dst = out_edge + (rowbase + r) * CZv;
            dst[l] = (v0 - mean) * rstd * ge0 + be0;
            dst[32 + l] = (v1 - mean) * rstd * ge1 + be1;
        }
    }
}

// ===========================================================================
extern "C" void kernel_launch(void* const* d_in, const int* in_sizes, int n_in,
                              void* d_out, int out_size) {
    const int* seq_idx = (const int*)d_in[0];
    const float* seq_feat = (const float*)d_in[1];
    const float* timestep = (const float*)d_in[2];
    const float* frame_mask = (const float*)d_in[3];
    const float* W_npos = (const float*)d_in[4];
    const float* b_npos = (const float*)d_in[5];
    const float* W_ntf = (const float*)d_in[6];
    const float* b_ntf = (const float*)d_in[7];
    const float* W_ntime = (const float*)d_in[8];
    const float* b_ntime = (const float*)d_in[9];
    const float* W_n1 = (const float*)d_in[10];
    const float* b_n1 = (const float*)d_in[11];
    const float* W_n2 = (const float*)d_in[12];
    const float* b_n2 = (const float*)d_in[13];
    const float* g_n = (const float*)d_in[14];
    const float* be_n = (const float*)d_in[15];
    const float* W_epos = (const float*)d_in[16];
    const float* b_epos = (const float*)d_in[17];
    const float* W_etf = (const float*)d_in[18];
    const float* b_etf = (const float*)d_in[19];
    const float* W_etime = (const float*)d_in[20];
    const float* b_etime = (const float*)d_in[21];
    const float* W_e1 = (const float*)d_in[22];
    const float* b_e1 = (const float*)d_in[23];
    const float* W_e2 = (const float*)d_in[24];
    const float* b_e2 = (const float*)d_in[25];
    const float* g_e = (const float*)d_in[26];
    const float* be_e = (const float*)d_in[27];

    float* out = (float*)d_out;
    float* out_seq = out;
    float* out_edge = out + NB * NN * CSv;

    static int configured = 0;
    if (!configured) {
        cudaFuncSetAttribute(edge_kernel, cudaFuncAttributeMaxDynamicSharedMemorySize,
                             EDGE_SMEM_BYTES);
        configured = 1;
    }

    setup_kernel<<<TBLK + NODEB + 64, 256>>>(
        seq_idx, seq_feat, timestep, frame_mask,
        W_npos, b_npos, W_ntf, b_ntf, W_ntime, b_ntime,
        W_n1, b_n1, W_n2, b_n2, g_n, be_n,
        W_epos, b_epos, b_etf, b_etime, W_etf, W_etime,
        W_e1, W_e2, out_seq);
    edge_kernel<<<NB * NN * 3, 256, EDGE_SMEM_BYTES>>>(seq_idx, b_e1, b_e2,
                                                       g_e, be_e, out_edge);
}

// round 16
// speedup vs baseline: 1.1712x; 1.0673x over previous
#include <cuda_runtime.h>
#include <cuda_fp16.h>
#include <cstdint>

#define NB 2
#define NN 384
#define TFv 22
#define POSv 32
#define TPROJv 33
#define CSv 256
#define CZv 128
#define LN_EPS 1e-5f
#define PI_F 3.14159265358979323846f

__device__ float g_table[2048 * CZv];
__device__ float g_eL[NB * NN * CZv];
__device__ float g_eR[NB * NN * CZv];
__device__ __half g_W1f[CZv * CZv], g_W2f[CZv * CZv];

// ---------------------------------------------------------------------------
// helpers
// ---------------------------------------------------------------------------
__device__ __forceinline__ uint32_t smem_u32(const void* p) {
    uint32_t a;
    asm("{ .reg .u64 t; cvta.to.shared.u64 t, %1; cvt.u32.u64 %0, t; }"
        : "=r"(a) : "l"(p));
    return a;
}
__device__ __forceinline__ uint32_t packh2(float r0, float r1) {
    __half2 v = __floats2half2_rn(r0, r1);
    return *reinterpret_cast<uint32_t*>(&v);
}
__device__ __forceinline__ void mma16816(float* c, uint32_t a0, uint32_t a1,
                                         uint32_t a2, uint32_t a3,
                                         uint32_t b0, uint32_t b1) {
    asm volatile(
        "mma.sync.aligned.m16n8k16.row.col.f32.f16.f16.f32 "
        "{%0,%1,%2,%3}, {%4,%5,%6,%7}, {%8,%9}, {%0,%1,%2,%3};"
        : "+f"(c[0]), "+f"(c[1]), "+f"(c[2]), "+f"(c[3])
        : "r"(a0), "r"(a1), "r"(a2), "r"(a3), "r"(b0), "r"(b1));
}
__device__ __forceinline__ void ldsm_x4(uint32_t& r0, uint32_t& r1,
                                        uint32_t& r2, uint32_t& r3, uint32_t addr) {
    asm volatile("ldmatrix.sync.aligned.m8n8.x4.shared.b16 {%0,%1,%2,%3}, [%4];"
                 : "=r"(r0), "=r"(r1), "=r"(r2), "=r"(r3) : "r"(addr));
}

// ---------------------------------------------------------------------------
// Fused setup kernel (unchanged — correctness proven).
// ---------------------------------------------------------------------------
#define NR 8
#define TBLK 1024
#define NODEB (NB * NN / NR)   // 96

__global__ __launch_bounds__(256) void setup_kernel(
    const int* __restrict__ seq_idx, const float* __restrict__ seq_feat,
    const float* __restrict__ timestep, const float* __restrict__ frame_mask,
    const float* __restrict__ W_npos, const float* __restrict__ b_npos,
    const float* __restrict__ W_ntf, const float* __restrict__ b_ntf,
    const float* __restrict__ W_ntime, const float* __restrict__ b_ntime,
    const float* __restrict__ W_n1, const float* __restrict__ b_n1,
    const float* __restrict__ W_n2, const float* __restrict__ b_n2,
    const float* __restrict__ g_n, const float* __restrict__ be_n,
    const float* __restrict__ W_epos, const float* __restrict__ b_epos,
    const float* __restrict__ b_etf, const float* __restrict__ b_etime,
    const float* __restrict__ W_etf, const float* __restrict__ W_etime,
    const float* __restrict__ W_e1, const float* __restrict__ W_e2,
    float* __restrict__ out_seq) {
    __shared__ float su[4352];
    const int tid = threadIdx.x;
    const int bid = blockIdx.x;

    if (bid < TBLK) {
        float* sWe = su;
        float* emb = su + 4224;
        const int half = tid >> 7, c = tid & 127;
        for (int m = tid; m < CZv * POSv; m += 256)
            sWe[(m >> 5) * 33 + (m & 31)] = W_epos[m];
        const int relv = bid * 2 + half - 1000;
        if (c < 16) {
            float p = powf(2056.0f, (float)c * (1.0f / 16.0f));
            float ang = ((float)relv * PI_F) / p;
            emb[half * 32 + c] = sinf(ang);
            emb[half * 32 + c + 16] = cosf(ang);
        }
        __syncthreads();
        float acc = b_epos[c] + b_etf[c] + b_etime[c];
#pragma unroll
        for (int k = 0; k < POSv; k++) acc += emb[half * 32 + k] * sWe[c * 33 + k];
        g_table[(bid * 2 + half) * CZv + c] = acc;
        return;
    }
    if (bid >= TBLK + NODEB) {
        int t = (bid - TBLK - NODEB) * 256 + tid;
        g_W1f[t] = __float2half_rn(W_e1[t]);
        g_W2f[t] = __float2half_rn(W_e2[t]);
        return;
    }

    float (*spemb)[POSv] = (float(*)[POSv])su;
    float (*stemb)[36] = (float(*)[36])(su + 256);
    float (*sfeat)[24] = (float(*)[24])(su + 544);
    float (*sx)[CSv] = (float(*)[CSv])(su + 736);
    const int row0 = (bid - TBLK) * NR;

    {
        const int r = tid >> 5, j = tid & 31;
        const int row = row0 + r;
        const int b = row / NN;
        if (j < TFv) sfeat[r][j] = seq_feat[row * TFv + j];
        if (j < 16) {
            float p = powf(2056.0f, (float)j * (1.0f / 16.0f));
            float ang = ((float)seq_idx[row] * PI_F) / p;
            spemb[r][j] = sinf(ang);
            spemb[r][j + 16] = cosf(ang);
            float fm = frame_mask[row];
            float tt = timestep[b] * fm;
            float fr = expf(-0.6140226914650789f * (float)j);
            float a2 = tt * fr;
            stemb[r][j] = sinf(a2);
            stemb[r][j + 16] = cosf(a2);
            if (j == 0) stemb[r][32] = fm;
        }
    }
    __syncthreads();

    const int c = tid;
    float acc[NR];
    {
        float base = b_npos[c] + b_ntf[c] + b_ntime[c];
#pragma unroll
        for (int r = 0; r < NR; r++) acc[r] = base;
    }
#pragma unroll
    for (int k = 0; k < POSv; k++) {
        float wv = W_npos[c * POSv + k];
#pragma unroll
        for (int r = 0; r < NR; r++) acc[r] += spemb[r][k] * wv;
    }
#pragma unroll
    for (int k = 0; k < TFv; k++) {
        float wv = W_ntf[c * TFv + k];
#pragma unroll
        for (int r = 0; r < NR; r++) acc[r] += sfeat[r][k] * wv;
    }
#pragma unroll
    for (int k = 0; k < TPROJv; k++) {
        float wv = W_ntime[c * TPROJv + k];
#pragma unroll
        for (int r = 0; r < NR; r++) acc[r] += stemb[r][k] * wv;
    }
#pragma unroll
    for (int r = 0; r < NR; r++) sx[r][c] = fmaxf(acc[r], 0.0f);

    {
        const int c2 = tid & 127, half = tid >> 7;
        float e[NR];
#pragma unroll
        for (int r = 0; r < NR; r++) e[r] = 0.0f;
#pragma unroll
        for (int k = 0; k < TFv; k++) {
            float wv = W_etf[c2 * (2 * TFv) + half * TFv + k];
#pragma unroll
            for (int r = 0; r < NR; r++) e[r] += sfeat[r][k] * wv;
        }
#pragma unroll
        for (int k = 0; k < TPROJv; k++) {
            float wv = W_etime[c2 * (2 * TPROJv) + half * TPROJv + k];
#pragma unroll
            for (int r = 0; r < NR; r++) e[r] += stemb[r][k] * wv;
        }
        float* dst = half ? g_eR : g_eL;
#pragma unroll
        for (int r = 0; r < NR; r++) dst[(row0 + r) * CZv + c2] = e[r];
    }
    __syncthreads();

    float h[NR];
#pragma unroll
    for (int r = 0; r < NR; r++) h[r] = b_n1[c];
    {
        const float4* W1r = (const float4*)(W_n1 + c * CSv);
#pragma unroll 4
        for (int q = 0; q < CSv / 4; q++) {
            float4 wv = W1r[q];
#pragma unroll
            for (int r = 0; r < NR; r++) {
                float4 xv = *(const float4*)&sx[r][q * 4];
                h[r] += xv.x * wv.x + xv.y * wv.y + xv.z * wv.z + xv.w * wv.w;
            }
        }
    }
    __syncthreads();
#pragma unroll
    for (int r = 0; r < NR; r++) sx[r][c] = fmaxf(h[r], 0.0f);
    __syncthreads();

    float o[NR];
#pragma unroll
    for (int r = 0; r < NR; r++) o[r] = b_n2[c];
    {
        const float4* W2r = (const float4*)(W_n2 + c * CSv);
#pragma unroll 4
        for (int q = 0; q < CSv / 4; q++) {
            float4 wv = W2r[q];
#pragma unroll
            for (int r = 0; r < NR; r++) {
                float4 xv = *(const float4*)&sx[r][q * 4];
                o[r] += xv.x * wv.x + xv.y * wv.y + xv.z * wv.z + xv.w * wv.w;
            }
        }
    }
    __syncthreads();
#pragma unroll
    for (int r = 0; r < NR; r++) sx[r][c] = o[r];
    __syncthreads();

    {
        const int w = tid >> 5, l = tid & 31;
        float v[8];
#pragma unroll
        for (int g = 0; g < 8; g++) v[g] = sx[w][g * 32 + l];
        float s = 0.0f;
#pragma unroll
        for (int g = 0; g < 8; g++) s += v[g];
#pragma unroll
        for (int off = 16; off > 0; off >>= 1) s += __shfl_xor_sync(0xffffffffu, s, off);
        float mean = s * (1.0f / 256.0f);
        float sq = 0.0f;
#pragma unroll
        for (int g = 0; g < 8; g++) { float d = v[g] - mean; sq += d * d; }
#pragma unroll
        for (int off = 16; off > 0; off >>= 1) sq += __shfl_xor_sync(0xffffffffu, sq, off);
        float rstd = rsqrtf(sq * (1.0f / 256.0f) + LN_EPS);
        const int row = row0 + w;
#pragma unroll
        for (int g = 0; g < 8; g++) {
            int cc = g * 32 + l;
            out_seq[row * CSv + cc] = (v[g] - mean) * rstd * g_n[cc] + be_n[cc];
        }
    }
}

// ---------------------------------------------------------------------------
// Edge kernel v6: v5 with de-serialized front-end — warp-private rel
// (no s_rel smem), X gather issued immediately, overlapped with W1 staging;
// single block sync before GEMM1.
// ---------------------------------------------------------------------------
#define WSTR 68
#define XH_W 0
#define WS_W (128 * WSTR)
#define EDGE_SMEM_U32 (2 * 128 * WSTR + 8)
#define EDGE_SMEM_BYTES (EDGE_SMEM_U32 * 4)

__global__ __launch_bounds__(256, 2) void edge_kernel(
    const int* __restrict__ seq_idx,
    const float* __restrict__ b_e1, const float* __restrict__ b_e2,
    const float* __restrict__ g_e, const float* __restrict__ be_e,
    float* __restrict__ out_edge) {
    extern __shared__ uint32_t smw[];
    uint32_t* Xh = smw + XH_W;
    uint32_t* Ws = smw + WS_W;

    const int tid = threadIdx.x, w = tid >> 5, l = tid & 31;
    const int g = l >> 2, tig = l & 3;
    const int m0 = w * 16;
    const int bid = blockIdx.x;
    const int jt = bid % 3, i = (bid / 3) % NN, b = bid / (3 * NN);
    const int j0 = jt * 128;

    const uint32_t sb = smem_u32(smw);
    const int l16 = l & 15, lhi = l >> 4;
    const uint32_t aAddr = sb + ((m0 + l16) * WSTR + lhi * 4) * 4;       // X (Xh)
    const int nB = (l & 7) + (lhi << 3);
    const int kofB = ((l >> 3) & 1) << 2;
    const uint32_t bAddr1 = sb + (WS_W + nB * WSTR + kofB) * 4;          // W1 (Ws)
    const uint32_t bAddr2 = sb + (nB * WSTR + kofB) * 4;                 // W2 (Xh)

    // ---- warp-private rel for own 16 rows (no smem, no block sync) ----
    int myrel;
    {
        int idx_i = __ldg(seq_idx + b * NN + i);
        int idx_j = __ldg(seq_idx + b * NN + j0 + m0 + l16);
        myrel = min(max(idx_i - idx_j + 1000, 0), 2047);
    }

    // ---- X build (own 16 rows), single fp16 — issues global gathers now ----
    {
        const float4 Lv = ((const float4*)(g_eL + (size_t)(b * NN + i) * CZv))[l];
        unsigned long long* Xh64 = (unsigned long long*)Xh;
#pragma unroll 4
        for (int it = 0; it < 16; it++) {
            const int r = m0 + it;
            const int rel = __shfl_sync(0xffffffffu, myrel, it);
            float4 tv = ((const float4*)(g_table + (size_t)rel * CZv))[l];
            float4 rv = ((const float4*)(g_eR + (size_t)(b * NN + j0 + r) * CZv))[l];
            uint32_t h01 = packh2(fmaxf(tv.x + Lv.x + rv.x, 0.0f),
                                  fmaxf(tv.y + Lv.y + rv.y, 0.0f));
            uint32_t h23 = packh2(fmaxf(tv.z + Lv.z + rv.z, 0.0f),
                                  fmaxf(tv.w + Lv.w + rv.w, 0.0f));
            Xh64[r * 34 + l] = ((unsigned long long)h23 << 32) | h01;
        }
    }

    // ---- W1 stage overlapped (cooperative; disjoint smem region) ----
    {
        const float4* Wsrc = (const float4*)g_W1f;
        for (int m = tid; m < 2048; m += 256) {
            int n = m >> 4, c4 = m & 15;
            *(float4*)&Ws[n * WSTR + c4 * 4] = Wsrc[m];
        }
    }

    // Prefetch this warp's W2 slice into registers (hidden under GEMM1).
    float4 w2r[8];
    {
        const float4* Wsrc = (const float4*)g_W2f;
#pragma unroll
        for (int it = 0; it < 8; it++) {
            int idx = it * 32 + l;
            w2r[it] = Wsrc[(m0 + (idx >> 4)) * 16 + (idx & 15)];
        }
    }
    __syncthreads();   // sync #1: W1 staged (X rows are warp-local)

    // ---- GEMM1: acc1[16][4] = X(16 x k128, fp16) @ W1^T ----
    float acc1[16][4];
#pragma unroll
    for (int nt = 0; nt < 16; nt++)
#pragma unroll
        for (int e = 0; e < 4; e++) acc1[nt][e] = 0.0f;
#pragma unroll
    for (int kk = 0; kk < 8; kk++) {
        const uint32_t kb = kk * 32;
        uint32_t ah[4];
        ldsm_x4(ah[0], ah[1], ah[2], ah[3], aAddr + kb);
#pragma unroll
        for (int p = 0; p < 8; p++) {
            uint32_t bf[4];
            ldsm_x4(bf[0], bf[1], bf[2], bf[3], bAddr1 + p * (16 * WSTR * 4) + kb);
            mma16816(acc1[2 * p], ah[0], ah[1], ah[2], ah[3], bf[0], bf[1]);
            mma16816(acc1[2 * p + 1], ah[0], ah[1], ah[2], ah[3], bf[2], bf[3]);
        }
    }

    // ---- Transform: H = relu(acc1 + b_e1) -> single-fp16 A-fragments ----
    uint32_t Ah[8][4];
#pragma unroll
    for (int q = 0; q < 8; q++) {
        const int c0 = 16 * q + 2 * tig;
        const int c1 = c0 + 8;
        float b00 = __ldg(b_e1 + c0), b01 = __ldg(b_e1 + c0 + 1);
        float b10 = __ldg(b_e1 + c1), b11 = __ldg(b_e1 + c1 + 1);
        Ah[q][0] = packh2(fmaxf(acc1[2 * q][0] + b00, 0.0f),
                          fmaxf(acc1[2 * q][1] + b01, 0.0f));
        Ah[q][1] = packh2(fmaxf(acc1[2 * q][2] + b00, 0.0f),
                          fmaxf(acc1[2 * q][3] + b01, 0.0f));
        Ah[q][2] = packh2(fmaxf(acc1[2 * q + 1][0] + b10, 0.0f),
                          fmaxf(acc1[2 * q + 1][1] + b11, 0.0f));
        Ah[q][3] = packh2(fmaxf(acc1[2 * q + 1][2] + b10, 0.0f),
                          fmaxf(acc1[2 * q + 1][3] + b11, 0.0f));
    }

    // ---- Store prefetched W2 slice into OWN Xh rows (X dead for this warp) ----
    {
#pragma unroll
        for (int it = 0; it < 8; it++) {
            int idx = it * 32 + l;
            int rn = m0 + (idx >> 4), c4 = idx & 15;
            *(float4*)&Xh[rn * WSTR + c4 * 4] = w2r[it];
        }
    }
    __syncthreads();   // sync #2: all W2 slices staged

    // ---- GEMM2 in two 64-col halves (A = Ah regs, fp16; B = W2 in Xh) ----
    float sumA = 0.0f, sqA = 0.0f, sumB = 0.0f, sqB = 0.0f;
    float* E0 = (float*)(Ws + m0 * WSTR);   // own W1 slice (dead): park half0
    const float* ge = g_e;
    const float* bee = be_e;

    float acc2[8][4];
#pragma unroll
    for (int h = 0; h < 2; h++) {
#pragma unroll
        for (int nt = 0; nt < 8; nt++)
#pragma unroll
            for (int e = 0; e < 4; e++) acc2[nt][e] = 0.0f;
#pragma unroll
        for (int kk = 0; kk < 8; kk++) {
            const uint32_t kb = kk * 32;
#pragma unroll
            for (int p = 0; p < 4; p++) {
                uint32_t bf[4];
                ldsm_x4(bf[0], bf[1], bf[2], bf[3],
                        bAddr2 + (h * 4 + p) * (16 * WSTR * 4) + kb);
                mma16816(acc2[2 * p], Ah[kk][0], Ah[kk][1], Ah[kk][2], Ah[kk][3],
                         bf[0], bf[1]);
                mma16816(acc2[2 * p + 1], Ah[kk][0], Ah[kk][1], Ah[kk][2], Ah[kk][3],
                         bf[2], bf[3]);
            }
        }
#pragma unroll
        for (int nt = 0; nt < 8; nt++) {
            const int col = h * 64 + 8 * nt + 2 * tig;
            float bb0 = __ldg(b_e2 + col), bb1 = __ldg(b_e2 + col + 1);
            float v0 = acc2[nt][0] + bb0, v1 = acc2[nt][1] + bb1;
            float v2 = acc2[nt][2] + bb0, v3 = acc2[nt][3] + bb1;
            sumA += v0 + v1; sqA += v0 * v0 + v1 * v1;
            sumB += v2 + v3; sqB += v2 * v2 + v3 * v3;
            if (h == 0) {
                *(float2*)&E0[g * WSTR + 8 * nt + 2 * tig] = make_float2(v0, v1);
                *(float2*)&E0[(g + 8) * WSTR + 8 * nt + 2 * tig] = make_float2(v2, v3);
            } else {
                acc2[nt][0] = v0; acc2[nt][1] = v1;
                acc2[nt][2] = v2; acc2[nt][3] = v3;
            }
        }
    }

    // ---- LN stats over the 4-lane quad ----
#pragma unroll
    for (int off = 1; off <= 2; off <<= 1) {
        sumA += __shfl_xor_sync(0xffffffffu, sumA, off);
        sqA += __shfl_xor_sync(0xffffffffu, sqA, off);
        sumB += __shfl_xor_sync(0xffffffffu, sumB, off);
        sqB += __shfl_xor_sync(0xffffffffu, sqB, off);
    }
    const float mA = sumA * (1.0f / 128.0f);
    const float rA = rsqrtf(fmaxf(sqA * (1.0f / 128.0f) - mA * mA, 0.0f) + LN_EPS);
    const float mB = sumB * (1.0f / 128.0f);
    const float rB = rsqrtf(fmaxf(sqB * (1.0f / 128.0f) - mB * mB, 0.0f) + LN_EPS);

    const size_t rowbase = ((size_t)(b * NN + i) * NN + (j0 + m0));

    // half1 (cols 64..127) directly from registers
    {
        float* dstg = out_edge + (rowbase + g) * CZv;
        float* dstg8 = out_edge + (rowbase + g + 8) * CZv;
#pragma unroll
        for (int nt = 0; nt < 8; nt++) {
            const int col = 64 + 8 * nt + 2 * tig;
            float ge0 = __ldg(ge + col), ge1 = __ldg(ge + col + 1);
            float be0 = __ldg(bee + col), be1 = __ldg(bee + col + 1);
            *(float2*)&dstg[col] = make_float2(
                (acc2[nt][0] - mA) * rA * ge0 + be0,
                (acc2[nt][1] - mA) * rA * ge1 + be1);
            *(float2*)&dstg8[col] = make_float2(
                (acc2[nt][2] - mB) * rB * ge0 + be0,
                (acc2[nt][3] - mB) * rB * ge1 + be1);
        }
    }
    __syncwarp();

    // half0 (cols 0..63) coalesced from E0 with shuffled stats
    {
        const float ge0 = ge[l], ge1 = ge[32 + l];
        const float be0 = bee[l], be1 = bee[32 + l];
#pragma unroll 2
        for (int r = 0; r < 16; r++) {
            const int src = 4 * (r & 7);
            float m1 = __shfl_sync(0xffffffffu, mA, src);
            float m2 = __shfl_sync(0xffffffffu, mB, src);
            float r1 = __shfl_sync(0xffffffffu, rA, src);
            float r2 = __shfl_sync(0xffffffffu, rB, src);
            float mean = (r < 8) ? m1 : m2;
            float rstd = (r < 8) ? r1 : r2;
            float v0 = E0[r * WSTR + l];
            float v1 = E0[r * WSTR + 32 + l];
            float* dst = out_edge + (rowbase + r) * CZv;
            dst[l] = (v0 - mean) * rstd * ge0 + be0;
            dst[32 + l] = (v1 - mean) * rstd * ge1 + be1;
        }
    }
}

// ===========================================================================
extern "C" void kernel_launch(void* const* d_in, const int* in_sizes, int n_in,
                              void* d_out, int out_size) {
    const int* seq_idx = (const int*)d_in[0];
    const float* seq_feat = (const float*)d_in[1];
    const float* timestep = (const float*)d_in[2];
    const float* frame_mask = (const float*)d_in[3];
    const float* W_npos = (const float*)d_in[4];
    const float* b_npos = (const float*)d_in[5];
    const float* W_ntf = (const float*)d_in[6];
    const float* b_ntf = (const float*)d_in[7];
    const float* W_ntime = (const float*)d_in[8];
    const float* b_ntime = (const float*)d_in[9];
    const float* W_n1 = (const float*)d_in[10];
    const float* b_n1 = (const float*)d_in[11];
    const float* W_n2 = (const float*)d_in[12];
    const float* b_n2 = (const float*)d_in[13];
    const float* g_n = (const float*)d_in[14];
    const float* be_n = (const float*)d_in[15];
    const float* W_epos = (const float*)d_in[16];
    const float* b_epos = (const float*)d_in[17];
    const float* W_etf = (const float*)d_in[18];
    const float* b_etf = (const float*)d_in[19];
    const float* W_etime = (const float*)d_in[20];
    const float* b_etime = (const float*)d_in[21];
    const float* W_e1 = (const float*)d_in[22];
    const float* b_e1 = (const float*)d_in[23];
    const float* W_e2 = (const float*)d_in[24];
    const float* b_e2 = (const float*)d_in[25];
    const float* g_e = (const float*)d_in[26];
    const float* be_e = (const float*)d_in[27];

    float* out = (float*)d_out;
    float* out_seq = out;
    float* out_edge = out + NB * NN * CSv;

    static int configured = 0;
    if (!configured) {
        cudaFuncSetAttribute(edge_kernel, cudaFuncAttributeMaxDynamicSharedMemorySize,
                             EDGE_SMEM_BYTES);
        configured = 1;
    }

    setup_kernel<<<TBLK + NODEB + 64, 256>>>(
        seq_idx, seq_feat, timestep, frame_mask,
        W_npos, b_npos, W_ntf, b_ntf, W_ntime, b_ntime,
        W_n1, b_n1, W_n2, b_n2, g_n, be_n,
        W_epos, b_epos, b_etf, b_etime, W_etf, W_etime,
        W_e1, W_e2, out_seq);
    edge_kernel<<<NB * NN * 3, 256, EDGE_SMEM_BYTES>>>(seq_idx, b_e1, b_e2,
                                                       g_e, be_e, out_edge);
}

// round 17
// speedup vs baseline: 1.2489x; 1.0664x over previous
#include <cuda_runtime.h>
#include <cuda_fp16.h>
#include <cstdint>

#define NB 2
#define NN 384
#define TFv 22
#define POSv 32
#define TPROJv 33
#define CSv 256
#define CZv 128
#define LN_EPS 1e-5f
#define PI_F 3.14159265358979323846f

#define NTILES (NB * NN * 3)   // 2304
#define EGRID 304              // persistent CTAs (2 per SM on 152 SMs)

__device__ float g_table[2048 * CZv];
__device__ float g_eL[NB * NN * CZv];
__device__ float g_eR[NB * NN * CZv];
__device__ __half g_W1f[CZv * CZv], g_W2f[CZv * CZv];

// ---------------------------------------------------------------------------
// helpers
// ---------------------------------------------------------------------------
__device__ __forceinline__ uint32_t smem_u32(const void* p) {
    uint32_t a;
    asm("{ .reg .u64 t; cvta.to.shared.u64 t, %1; cvt.u32.u64 %0, t; }"
        : "=r"(a) : "l"(p));
    return a;
}
__device__ __forceinline__ uint32_t packh2(float r0, float r1) {
    __half2 v = __floats2half2_rn(r0, r1);
    return *reinterpret_cast<uint32_t*>(&v);
}
__device__ __forceinline__ void mma16816(float* c, uint32_t a0, uint32_t a1,
                                         uint32_t a2, uint32_t a3,
                                         uint32_t b0, uint32_t b1) {
    asm volatile(
        "mma.sync.aligned.m16n8k16.row.col.f32.f16.f16.f32 "
        "{%0,%1,%2,%3}, {%4,%5,%6,%7}, {%8,%9}, {%0,%1,%2,%3};"
        : "+f"(c[0]), "+f"(c[1]), "+f"(c[2]), "+f"(c[3])
        : "r"(a0), "r"(a1), "r"(a2), "r"(a3), "r"(b0), "r"(b1));
}
__device__ __forceinline__ void ldsm_x4(uint32_t& r0, uint32_t& r1,
                                        uint32_t& r2, uint32_t& r3, uint32_t addr) {
    asm volatile("ldmatrix.sync.aligned.m8n8.x4.shared.b16 {%0,%1,%2,%3}, [%4];"
                 : "=r"(r0), "=r"(r1), "=r"(r2), "=r"(r3) : "r"(addr));
}

// ---------------------------------------------------------------------------
// Fused setup kernel (unchanged — correctness proven).
// ---------------------------------------------------------------------------
#define NR 8
#define TBLK 1024
#define NODEB (NB * NN / NR)   // 96

__global__ __launch_bounds__(256) void setup_kernel(
    const int* __restrict__ seq_idx, const float* __restrict__ seq_feat,
    const float* __restrict__ timestep, const float* __restrict__ frame_mask,
    const float* __restrict__ W_npos, const float* __restrict__ b_npos,
    const float* __restrict__ W_ntf, const float* __restrict__ b_ntf,
    const float* __restrict__ W_ntime, const float* __restrict__ b_ntime,
    const float* __restrict__ W_n1, const float* __restrict__ b_n1,
    const float* __restrict__ W_n2, const float* __restrict__ b_n2,
    const float* __restrict__ g_n, const float* __restrict__ be_n,
    const float* __restrict__ W_epos, const float* __restrict__ b_epos,
    const float* __restrict__ b_etf, const float* __restrict__ b_etime,
    const float* __restrict__ W_etf, const float* __restrict__ W_etime,
    const float* __restrict__ W_e1, const float* __restrict__ W_e2,
    float* __restrict__ out_seq) {
    __shared__ float su[4352];
    const int tid = threadIdx.x;
    const int bid = blockIdx.x;

    if (bid < TBLK) {
        float* sWe = su;
        float* emb = su + 4224;
        const int half = tid >> 7, c = tid & 127;
        for (int m = tid; m < CZv * POSv; m += 256)
            sWe[(m >> 5) * 33 + (m & 31)] = W_epos[m];
        const int relv = bid * 2 + half - 1000;
        if (c < 16) {
            float p = powf(2056.0f, (float)c * (1.0f / 16.0f));
            float ang = ((float)relv * PI_F) / p;
            emb[half * 32 + c] = sinf(ang);
            emb[half * 32 + c + 16] = cosf(ang);
        }
        __syncthreads();
        float acc = b_epos[c] + b_etf[c] + b_etime[c];
#pragma unroll
        for (int k = 0; k < POSv; k++) acc += emb[half * 32 + k] * sWe[c * 33 + k];
        g_table[(bid * 2 + half) * CZv + c] = acc;
        return;
    }
    if (bid >= TBLK + NODEB) {
        int t = (bid - TBLK - NODEB) * 256 + tid;
        g_W1f[t] = __float2half_rn(W_e1[t]);
        g_W2f[t] = __float2half_rn(W_e2[t]);
        return;
    }

    float (*spemb)[POSv] = (float(*)[POSv])su;
    float (*stemb)[36] = (float(*)[36])(su + 256);
    float (*sfeat)[24] = (float(*)[24])(su + 544);
    float (*sx)[CSv] = (float(*)[CSv])(su + 736);
    const int row0 = (bid - TBLK) * NR;

    {
        const int r = tid >> 5, j = tid & 31;
        const int row = row0 + r;
        const int b = row / NN;
        if (j < TFv) sfeat[r][j] = seq_feat[row * TFv + j];
        if (j < 16) {
            float p = powf(2056.0f, (float)j * (1.0f / 16.0f));
            float ang = ((float)seq_idx[row] * PI_F) / p;
            spemb[r][j] = sinf(ang);
            spemb[r][j + 16] = cosf(ang);
            float fm = frame_mask[row];
            float tt = timestep[b] * fm;
            float fr = expf(-0.6140226914650789f * (float)j);
            float a2 = tt * fr;
            stemb[r][j] = sinf(a2);
            stemb[r][j + 16] = cosf(a2);
            if (j == 0) stemb[r][32] = fm;
        }
    }
    __syncthreads();

    const int c = tid;
    float acc[NR];
    {
        float base = b_npos[c] + b_ntf[c] + b_ntime[c];
#pragma unroll
        for (int r = 0; r < NR; r++) acc[r] = base;
    }
#pragma unroll
    for (int k = 0; k < POSv; k++) {
        float wv = W_npos[c * POSv + k];
#pragma unroll
        for (int r = 0; r < NR; r++) acc[r] += spemb[r][k] * wv;
    }
#pragma unroll
    for (int k = 0; k < TFv; k++) {
        float wv = W_ntf[c * TFv + k];
#pragma unroll
        for (int r = 0; r < NR; r++) acc[r] += sfeat[r][k] * wv;
    }
#pragma unroll
    for (int k = 0; k < TPROJv; k++) {
        float wv = W_ntime[c * TPROJv + k];
#pragma unroll
        for (int r = 0; r < NR; r++) acc[r] += stemb[r][k] * wv;
    }
#pragma unroll
    for (int r = 0; r < NR; r++) sx[r][c] = fmaxf(acc[r], 0.0f);

    {
        const int c2 = tid & 127, half = tid >> 7;
        float e[NR];
#pragma unroll
        for (int r = 0; r < NR; r++) e[r] = 0.0f;
#pragma unroll
        for (int k = 0; k < TFv; k++) {
            float wv = W_etf[c2 * (2 * TFv) + half * TFv + k];
#pragma unroll
            for (int r = 0; r < NR; r++) e[r] += sfeat[r][k] * wv;
        }
#pragma unroll
        for (int k = 0; k < TPROJv; k++) {
            float wv = W_etime[c2 * (2 * TPROJv) + half * TPROJv + k];
#pragma unroll
            for (int r = 0; r < NR; r++) e[r] += stemb[r][k] * wv;
        }
        float* dst = half ? g_eR : g_eL;
#pragma unroll
        for (int r = 0; r < NR; r++) dst[(row0 + r) * CZv + c2] = e[r];
    }
    __syncthreads();

    float h[NR];
#pragma unroll
    for (int r = 0; r < NR; r++) h[r] = b_n1[c];
    {
        const float4* W1r = (const float4*)(W_n1 + c * CSv);
#pragma unroll 4
        for (int q = 0; q < CSv / 4; q++) {
            float4 wv = W1r[q];
#pragma unroll
            for (int r = 0; r < NR; r++) {
                float4 xv = *(const float4*)&sx[r][q * 4];
                h[r] += xv.x * wv.x + xv.y * wv.y + xv.z * wv.z + xv.w * wv.w;
            }
        }
    }
    __syncthreads();
#pragma unroll
    for (int r = 0; r < NR; r++) sx[r][c] = fmaxf(h[r], 0.0f);
    __syncthreads();

    float o[NR];
#pragma unroll
    for (int r = 0; r < NR; r++) o[r] = b_n2[c];
    {
        const float4* W2r = (const float4*)(W_n2 + c * CSv);
#pragma unroll 4
        for (int q = 0; q < CSv / 4; q++) {
            float4 wv = W2r[q];
#pragma unroll
            for (int r = 0; r < NR; r++) {
                float4 xv = *(const float4*)&sx[r][q * 4];
                o[r] += xv.x * wv.x + xv.y * wv.y + xv.z * wv.z + xv.w * wv.w;
            }
        }
    }
    __syncthreads();
#pragma unroll
    for (int r = 0; r < NR; r++) sx[r][c] = o[r];
    __syncthreads();

    {
        const int w = tid >> 5, l = tid & 31;
        float v[8];
#pragma unroll
        for (int g = 0; g < 8; g++) v[g] = sx[w][g * 32 + l];
        float s = 0.0f;
#pragma unroll
        for (int g = 0; g < 8; g++) s += v[g];
#pragma unroll
        for (int off = 16; off > 0; off >>= 1) s += __shfl_xor_sync(0xffffffffu, s, off);
        float mean = s * (1.0f / 256.0f);
        float sq = 0.0f;
#pragma unroll
        for (int g = 0; g < 8; g++) { float d = v[g] - mean; sq += d * d; }
#pragma unroll
        for (int off = 16; off > 0; off >>= 1) sq += __shfl_xor_sync(0xffffffffu, sq, off);
        float rstd = rsqrtf(sq * (1.0f / 256.0f) + LN_EPS);
        const int row = row0 + w;
#pragma unroll
        for (int g = 0; g < 8; g++) {
            int cc = g * 32 + l;
            out_seq[row * CSv + cc] = (v[g] - mean) * rstd * g_n[cc] + be_n[cc];
        }
    }
}

// ---------------------------------------------------------------------------
// Edge kernel v7: PERSISTENT. W1/W2 staged to smem once per CTA; warps then
// loop tiles fully autonomously (zero block syncs in the loop).
// smem: X (also E0 park) | W1 | W2.
// ---------------------------------------------------------------------------
#define WSTR 68
#define XH_W 0
#define W1_W (128 * WSTR)
#define W2_W (2 * 128 * WSTR)
#define EDGE_SMEM_U32 (3 * 128 * WSTR + 8)
#define EDGE_SMEM_BYTES (EDGE_SMEM_U32 * 4)

__global__ __launch_bounds__(256, 2) void edge_kernel(
    const int* __restrict__ seq_idx,
    const float* __restrict__ b_e1, const float* __restrict__ b_e2,
    const float* __restrict__ g_e, const float* __restrict__ be_e,
    float* __restrict__ out_edge) {
    extern __shared__ uint32_t smw[];
    uint32_t* Xh = smw + XH_W;

    const int tid = threadIdx.x, w = tid >> 5, l = tid & 31;
    const int g = l >> 2, tig = l & 3;
    const int m0 = w * 16;

    const uint32_t sb = smem_u32(smw);
    const int l16 = l & 15, lhi = l >> 4;
    const uint32_t aAddr = sb + ((m0 + l16) * WSTR + lhi * 4) * 4;       // X
    const int nB = (l & 7) + (lhi << 3);
    const int kofB = ((l >> 3) & 1) << 2;
    const uint32_t bAddr1 = sb + (W1_W + nB * WSTR + kofB) * 4;          // W1
    const uint32_t bAddr2 = sb + (W2_W + nB * WSTR + kofB) * 4;          // W2

    // ---- one-time W1/W2 staging (cooperative) ----
    {
        const float4* W1src = (const float4*)g_W1f;
        const float4* W2src = (const float4*)g_W2f;
        for (int m = tid; m < 2048; m += 256) {
            int n = m >> 4, c4 = m & 15;
            *(float4*)&smw[W1_W + n * WSTR + c4 * 4] = W1src[m];
            *(float4*)&smw[W2_W + n * WSTR + c4 * 4] = W2src[m];
        }
    }
    __syncthreads();   // ONLY block sync — everything after is warp-local

    float* E0 = (float*)(Xh + m0 * WSTR);   // own X rows double as E0 park

    for (int t = blockIdx.x; t < NTILES; t += EGRID) {
        const int jt = t % 3, i = (t / 3) % NN, b = t / (3 * NN);
        const int j0 = jt * 128;

        // ---- warp-private rel + X build (own 16 rows, fp16) ----
        int myrel;
        {
            int idx_i = __ldg(seq_idx + b * NN + i);
            int idx_j = __ldg(seq_idx + b * NN + j0 + m0 + l16);
            myrel = min(max(idx_i - idx_j + 1000, 0), 2047);
        }
        {
            const float4 Lv = ((const float4*)(g_eL + (size_t)(b * NN + i) * CZv))[l];
            unsigned long long* Xh64 = (unsigned long long*)Xh;
#pragma unroll 4
            for (int it = 0; it < 16; it++) {
                const int r = m0 + it;
                const int rel = __shfl_sync(0xffffffffu, myrel, it);
                float4 tv = ((const float4*)(g_table + (size_t)rel * CZv))[l];
                float4 rv = ((const float4*)(g_eR + (size_t)(b * NN + j0 + r) * CZv))[l];
                uint32_t h01 = packh2(fmaxf(tv.x + Lv.x + rv.x, 0.0f),
                                      fmaxf(tv.y + Lv.y + rv.y, 0.0f));
                uint32_t h23 = packh2(fmaxf(tv.z + Lv.z + rv.z, 0.0f),
                                      fmaxf(tv.w + Lv.w + rv.w, 0.0f));
                Xh64[r * 34 + l] = ((unsigned long long)h23 << 32) | h01;
            }
        }
        __syncwarp();

        // ---- GEMM1: acc1[16][4] = X @ W1^T ----
        float acc1[16][4];
#pragma unroll
        for (int nt = 0; nt < 16; nt++)
#pragma unroll
            for (int e = 0; e < 4; e++) acc1[nt][e] = 0.0f;
#pragma unroll
        for (int kk = 0; kk < 8; kk++) {
            const uint32_t kb = kk * 32;
            uint32_t ah[4];
            ldsm_x4(ah[0], ah[1], ah[2], ah[3], aAddr + kb);
#pragma unroll
            for (int p = 0; p < 8; p++) {
                uint32_t bf[4];
                ldsm_x4(bf[0], bf[1], bf[2], bf[3], bAddr1 + p * (16 * WSTR * 4) + kb);
                mma16816(acc1[2 * p], ah[0], ah[1], ah[2], ah[3], bf[0], bf[1]);
                mma16816(acc1[2 * p + 1], ah[0], ah[1], ah[2], ah[3], bf[2], bf[3]);
            }
        }
        __syncwarp();   // GEMM1 A-reads done before E0 overwrites X rows

        // ---- Transform: H = relu(acc1 + b_e1) -> single-fp16 A-fragments ----
        uint32_t Ah[8][4];
#pragma unroll
        for (int q = 0; q < 8; q++) {
            const int c0 = 16 * q + 2 * tig;
            const int c1 = c0 + 8;
            float b00 = __ldg(b_e1 + c0), b01 = __ldg(b_e1 + c0 + 1);
            float b10 = __ldg(b_e1 + c1), b11 = __ldg(b_e1 + c1 + 1);
            Ah[q][0] = packh2(fmaxf(acc1[2 * q][0] + b00, 0.0f),
                              fmaxf(acc1[2 * q][1] + b01, 0.0f));
            Ah[q][1] = packh2(fmaxf(acc1[2 * q][2] + b00, 0.0f),
                              fmaxf(acc1[2 * q][3] + b01, 0.0f));
            Ah[q][2] = packh2(fmaxf(acc1[2 * q + 1][0] + b10, 0.0f),
                              fmaxf(acc1[2 * q + 1][1] + b11, 0.0f));
            Ah[q][3] = packh2(fmaxf(acc1[2 * q + 1][2] + b10, 0.0f),
                              fmaxf(acc1[2 * q + 1][3] + b11, 0.0f));
        }

        // ---- GEMM2 in two 64-col halves (A = Ah regs; B = W2 persistent) ----
        float sumA = 0.0f, sqA = 0.0f, sumB = 0.0f, sqB = 0.0f;
        float acc2[8][4];
#pragma unroll
        for (int h = 0; h < 2; h++) {
#pragma unroll
            for (int nt = 0; nt < 8; nt++)
#pragma unroll
                for (int e = 0; e < 4; e++) acc2[nt][e] = 0.0f;
#pragma unroll
            for (int kk = 0; kk < 8; kk++) {
                const uint32_t kb = kk * 32;
#pragma unroll
                for (int p = 0; p < 4; p++) {
                    uint32_t bf[4];
                    ldsm_x4(bf[0], bf[1], bf[2], bf[3],
                            bAddr2 + (h * 4 + p) * (16 * WSTR * 4) + kb);
                    mma16816(acc2[2 * p], Ah[kk][0], Ah[kk][1], Ah[kk][2], Ah[kk][3],
                             bf[0], bf[1]);
                    mma16816(acc2[2 * p + 1], Ah[kk][0], Ah[kk][1], Ah[kk][2], Ah[kk][3],
                             bf[2], bf[3]);
                }
            }
#pragma unroll
            for (int nt = 0; nt < 8; nt++) {
                const int col = h * 64 + 8 * nt + 2 * tig;
                float bb0 = __ldg(b_e2 + col), bb1 = __ldg(b_e2 + col + 1);
                float v0 = acc2[nt][0] + bb0, v1 = acc2[nt][1] + bb1;
                float v2 = acc2[nt][2] + bb0, v3 = acc2[nt][3] + bb1;
                sumA += v0 + v1; sqA += v0 * v0 + v1 * v1;
                sumB += v2 + v3; sqB += v2 * v2 + v3 * v3;
                if (h == 0) {
                    *(float2*)&E0[g * WSTR + 8 * nt + 2 * tig] = make_float2(v0, v1);
                    *(float2*)&E0[(g + 8) * WSTR + 8 * nt + 2 * tig] = make_float2(v2, v3);
                } else {
                    acc2[nt][0] = v0; acc2[nt][1] = v1;
                    acc2[nt][2] = v2; acc2[nt][3] = v3;
                }
            }
        }

        // ---- LN stats over the 4-lane quad ----
#pragma unroll
        for (int off = 1; off <= 2; off <<= 1) {
            sumA += __shfl_xor_sync(0xffffffffu, sumA, off);
            sqA += __shfl_xor_sync(0xffffffffu, sqA, off);
            sumB += __shfl_xor_sync(0xffffffffu, sumB, off);
            sqB += __shfl_xor_sync(0xffffffffu, sqB, off);
        }
        const float mA = sumA * (1.0f / 128.0f);
        const float rA = rsqrtf(fmaxf(sqA * (1.0f / 128.0f) - mA * mA, 0.0f) + LN_EPS);
        const float mB = sumB * (1.0f / 128.0f);
        const float rB = rsqrtf(fmaxf(sqB * (1.0f / 128.0f) - mB * mB, 0.0f) + LN_EPS);

        const size_t rowbase = ((size_t)(b * NN + i) * NN + (j0 + m0));

        // half1 (cols 64..127) directly from registers
        {
            float* dstg = out_edge + (rowbase + g) * CZv;
            float* dstg8 = out_edge + (rowbase + g + 8) * CZv;
#pragma unroll
            for (int nt = 0; nt < 8; nt++) {
                const int col = 64 + 8 * nt + 2 * tig;
                float ge0 = __ldg(g_e + col), ge1 = __ldg(g_e + col + 1);
                float be0 = __ldg(be_e + col), be1 = __ldg(be_e + col + 1);
                *(float2*)&dstg[col] = make_float2(
                    (acc2[nt][0] - mA) * rA * ge0 + be0,
                    (acc2[nt][1] - mA) * rA * ge1 + be1);
                *(float2*)&dstg8[col] = make_float2(
                    (acc2[nt][2] - mB) * rB * ge0 + be0,
                    (acc2[nt][3] - mB) * rB * ge1 + be1);
            }
        }
        __syncwarp();   // E0 writes visible before cross-lane reads

        // half0 (cols 0..63) coalesced from E0 with shuffled stats
        {
            const float ge0 = g_e[l], ge1 = g_e[32 + l];
            const float be0 = be_e[l], be1 = be_e[32 + l];
#pragma unroll 2
            for (int r = 0; r < 16; r++) {
                const int src = 4 * (r & 7);
                float m1 = __shfl_sync(0xffffffffu, mA, src);
                float m2 = __shfl_sync(0xffffffffu, mB, src);
                float r1 = __shfl_sync(0xffffffffu, rA, src);
                float r2 = __shfl_sync(0xffffffffu, rB, src);
                float mean = (r < 8) ? m1 : m2;
                float rstd = (r < 8) ? r1 : r2;
                float v0 = E0[r * WSTR + l];
                float v1 = E0[r * WSTR + 32 + l];
                float* dst = out_edge + (rowbase + r) * CZv;
                dst[l] = (v0 - mean) * rstd * ge0 + be0;
                dst[32 + l] = (v1 - mean) * rstd * ge1 + be1;
            }
        }
        __syncwarp();   // E0 reads done before next tile's X build overwrites
    }
}

// ===========================================================================
extern "C" void kernel_launch(void* const* d_in, const int* in_sizes, int n_in,
                              void* d_out, int out_size) {
    const int* seq_idx = (const int*)d_in[0];
    const float* seq_feat = (const float*)d_in[1];
    const float* timestep = (const float*)d_in[2];
    const float* frame_mask = (const float*)d_in[3];
    const float* W_npos = (const float*)d_in[4];
    const float* b_npos = (const float*)d_in[5];
    const float* W_ntf = (const float*)d_in[6];
    const float* b_ntf = (const float*)d_in[7];
    const float* W_ntime = (const float*)d_in[8];
    const float* b_ntime = (const float*)d_in[9];
    const float* W_n1 = (const float*)d_in[10];
    const float* b_n1 = (const float*)d_in[11];
    const float* W_n2 = (const float*)d_in[12];
    const float* b_n2 = (const float*)d_in[13];
    const float* g_n = (const float*)d_in[14];
    const float* be_n = (const float*)d_in[15];
    const float* W_epos = (const float*)d_in[16];
    const float* b_epos = (const float*)d_in[17];
    const float* W_etf = (const float*)d_in[18];
    const float* b_etf = (const float*)d_in[19];
    const float* W_etime = (const float*)d_in[20];
    const float* b_etime = (const float*)d_in[21];
    const float* W_e1 = (const float*)d_in[22];
    const float* b_e1 = (const float*)d_in[23];
    const float* W_e2 = (const float*)d_in[24];
    const float* b_e2 = (const float*)d_in[25];
    const float* g_e = (const float*)d_in[26];
    const float* be_e = (const float*)d_in[27];

    float* out = (float*)d_out;
    float* out_seq = out;
    float* out_edge = out + NB * NN * CSv;

    static int configured = 0;
    if (!configured) {
        cudaFuncSetAttribute(edge_kernel, cudaFuncAttributeMaxDynamicSharedMemorySize,
                             EDGE_SMEM_BYTES);
        configured = 1;
    }

    setup_kernel<<<TBLK + NODEB + 64, 256>>>(
        seq_idx, seq_feat, timestep, frame_mask,
        W_npos, b_npos, W_ntf, b_ntf, W_ntime, b_ntime,
        W_n1, b_n1, W_n2, b_n2, g_n, be_n,
        W_epos, b_epos, b_etf, b_etime, W_etf, W_etime,
        W_e1, W_e2, out_seq);
    edge_kernel<<<EGRID, 256, EDGE_SMEM_BYTES>>>(seq_idx, b_e1, b_e2,
                                                 g_e, be_e, out_edge);
}